// round 14
// baseline (speedup 1.0000x reference)
#include <cuda_runtime.h>
#include <cuda_bf16.h>
#include <cstdint>
#include <cstddef>

#define NN   50000
#define NNP  50048      // padded rows for node scratch
#define NE   800000
#define NG   512
#define DD   101
#define PP   104        // fp32 node pitch (16B-aligned rows)
#define NKT  21         // logical k16 tiles = 3 regions * 7 (region width 112)

#define MT   256        // M tile
#define NT   128        // N tile
#define THR  512        // threads (16 warps)

// smem (bytes): As [256][116] u32 split A; Wc [2][56][136] u32; bias
#define SM_AS   118784
#define SM_WC   60928
#define SM_ALL  (SM_AS + SM_WC + 512)

// ---------------- scratch (device globals; no allocation) ----------------
__device__ float g_xp [(size_t)NNP * PP];   // x padded fp32
__device__ float g_agg[(size_t)NNP * PP];   // scatter-add target
__device__ float g_t  [(size_t)NNP * PP];   // MLP intermediate
__device__ float g_h1 [(size_t)NNP * PP];   // layer-1 output
__device__ float g_gp [NG * 200];           // pooled per-graph features

// ---------------- helpers ----------------
__device__ __forceinline__ void red4(float* p, float a, float b, float c, float d) {
    asm volatile("red.global.add.v4.f32 [%0], {%1,%2,%3,%4};"
                 :: "l"(p), "f"(a), "f"(b), "f"(c), "f"(d) : "memory");
}

__device__ __forceinline__ uint32_t packbf(float e, float o) {
    __nv_bfloat162 t = __floats2bfloat162_rn(e, o);   // e -> low 16 bits (even k)
    return *reinterpret_cast<uint32_t*>(&t);
}

__device__ __forceinline__ void bsplit2(float v0, float v1, uint32_t& hi, uint32_t& lo) {
    float h0 = __bfloat162float(__float2bfloat16(v0));
    float h1 = __bfloat162float(__float2bfloat16(v1));
    hi = packbf(h0, h1);
    lo = packbf(v0 - h0, v1 - h1);
}

__device__ __forceinline__ void mma16816(float c[4],
                                         uint32_t a0, uint32_t a1, uint32_t a2, uint32_t a3,
                                         uint32_t b0, uint32_t b1) {
    asm volatile(
        "mma.sync.aligned.m16n8k16.row.col.f32.bf16.bf16.f32 "
        "{%0,%1,%2,%3}, {%4,%5,%6,%7}, {%8,%9}, {%0,%1,%2,%3};"
        : "+f"(c[0]), "+f"(c[1]), "+f"(c[2]), "+f"(c[3])
        : "r"(a0), "r"(a1), "r"(a2), "r"(a3), "r"(b0), "r"(b1));
}

// plain pad: src [rows x srcPitch] -> dst [rows x PP] fp32 (zeros in pad cols)
__global__ void pad_plain_kernel(float* __restrict__ dst, const float* __restrict__ src,
                                 int rows, int srcPitch) {
    int t = blockIdx.x * blockDim.x + threadIdx.x;
    if (t < rows * PP) {
        int r = t / PP;
        int c = t - r * PP;
        dst[t] = (c < srcPitch) ? __ldg(&src[(size_t)r * srcPitch + c]) : 0.f;
    }
}

// ---------------- fused split + 3xBF16 K-expanded tensor-core GEMM ---------------
// A read as RAW fp32 [M x PAT] (rows contiguous; block span 16B-aligned).
// In-kernel split to smem: As16[row][0..111]=hi, [112..223]=lo (u32 pitch 116,
// conflict-free: 116 mod 32 = 20 -> g*20+tg distinct).  Logical K = 336:
// A regions [hi|lo|hi], B regions [hi|hi|lo] -> hiA*hiB + loA*hiB + hiA*loB.
// Mainloop: NO syncs, NO gmem — pure smem + HMMA.
// MODE 0: outp[m][n] = relu(C+bias) for n<pOut (A2 optional elementwise add input)
// MODE 1: v = relu(C+bias+xg[idx0[m]][n]); red4 into outp[idx1[m]]
// MODE 2: v = relu(C+bias);                red4 into outp[idx0[m]]  (idx0=batch)
template <int MODE, int PAT>
__global__ __launch_bounds__(THR, 1)
void gemm_fsp(const float* __restrict__ A1, const float* __restrict__ A2,
              const float* __restrict__ B,  const float* __restrict__ bias,
              int M, int N, int Korig,
              const int* __restrict__ idx0, const int* __restrict__ idx1,
              const float* __restrict__ xg,          // fp32 [x PP]
              float* __restrict__ outp, int pOut)
{
    extern __shared__ char sm[];
    uint32_t* AsU   = reinterpret_cast<uint32_t*>(sm);            // [256][116]
    uint32_t* WcU   = reinterpret_cast<uint32_t*>(sm + SM_AS);    // [2][56][136]
    float*    biasS = reinterpret_cast<float*>(sm + SM_AS + SM_WC);

    const int tid  = threadIdx.x;
    const int m0   = blockIdx.x * MT;
    const int n0   = blockIdx.y * NT;
    const int wid  = tid >> 5;
    const int lane = tid & 31;
    const int wm   = (wid >> 1) * 32;   // 0..224
    const int wn   = (wid & 1) * 64;
    const int g    = lane >> 2;
    const int tg   = lane & 3;

    // ---- zero As (covers pad cols + tail rows) ----
    {
        uint4 z = make_uint4(0, 0, 0, 0);
        uint4* p = reinterpret_cast<uint4*>(AsU);
        for (int i = tid; i < (MT * 116) / 4; i += THR) p[i] = z;
    }

    // ---- fill weight cache: hi plane + lo plane, packed bf16 k-pairs ----
    for (int it = tid; it < 56 * NT; it += THR) {
        int kp = it >> 7, n = it & 127;
        int ke = kp * 2, ko = ke + 1;
        bool nv = (n0 + n < N);
        float we = (nv && ke < Korig) ? __ldg(&B[(size_t)ke * N + n0 + n]) : 0.f;
        float wo = (nv && ko < Korig) ? __ldg(&B[(size_t)ko * N + n0 + n]) : 0.f;
        uint32_t hi, lo;
        bsplit2(we, wo, hi, lo);
        WcU[kp * 136 + n]            = hi;
        WcU[56 * 136 + kp * 136 + n] = lo;
    }
    if (tid < NT) biasS[tid] = (n0 + tid < N) ? __ldg(&bias[n0 + tid]) : 0.f;
    __syncthreads();   // As zeros + Wc visible

    // ---- convert: raw fp32 span -> split bf16 smem ----
    {
        __nv_bfloat16* as16 = reinterpret_cast<__nv_bfloat16*>(AsU);
        const float* a1 = A1 + (size_t)m0 * PAT;
        const int total = MT * PAT;
        if (A2) {
            const float* a2 = A2 + (size_t)m0 * PAT;
            for (int idx = tid; idx < total; idx += THR) {
                int row = idx / PAT, col = idx - row * PAT;
                if (m0 + row < M) {
                    float f = __ldg(a1 + idx) + __ldg(a2 + idx);
                    __nv_bfloat16 h = __float2bfloat16(f);
                    as16[row * 232 + col]       = h;
                    as16[row * 232 + 112 + col] = __float2bfloat16(f - __bfloat162float(h));
                }
            }
        } else {
            for (int idx = tid; idx < total; idx += THR) {
                int row = idx / PAT, col = idx - row * PAT;
                if (m0 + row < M) {
                    float f = __ldg(a1 + idx);
                    __nv_bfloat16 h = __float2bfloat16(f);
                    as16[row * 232 + col]       = h;
                    as16[row * 232 + 112 + col] = __float2bfloat16(f - __bfloat162float(h));
                }
            }
        }
    }
    __syncthreads();

    // ---- mainloop: 21 k16 tiles, all smem, no syncs ----
    float acc[2][8][4];
#pragma unroll
    for (int i = 0; i < 2; ++i)
#pragma unroll
        for (int j = 0; j < 8; ++j)
#pragma unroll
            for (int q = 0; q < 4; ++q) acc[i][j][q] = 0.f;

    for (int kt = 0; kt < NKT; ++kt) {
        const int r = (kt >= 14) ? 2 : (kt >= 7 ? 1 : 0);
        const int q = kt - ((r == 2) ? 14 : (r == 1 ? 7 : 0));
        const uint32_t* wb = WcU + ((r == 2) ? 56 * 136 : 0) + (q * 8) * 136;
        const int abase = ((r == 1) ? 56 : 0) + q * 8;

        uint32_t bfr[8][2];
#pragma unroll
        for (int j = 0; j < 8; ++j) {
            const int col = wn + j * 8 + g;
            bfr[j][0] = wb[tg * 136 + col];
            bfr[j][1] = wb[(tg + 4) * 136 + col];
        }
#pragma unroll
        for (int i = 0; i < 2; ++i) {
            const int mb = wm + i * 16 + g;
            uint32_t a0 = AsU[mb * 116 + abase + tg];
            uint32_t a1 = AsU[(mb + 8) * 116 + abase + tg];
            uint32_t a2 = AsU[mb * 116 + abase + tg + 4];
            uint32_t a3 = AsU[(mb + 8) * 116 + abase + tg + 4];
#pragma unroll
            for (int j = 0; j < 8; ++j)
                mma16816(acc[i][j], a0, a1, a2, a3, bfr[j][0], bfr[j][1]);
        }
    }

    // ---------------- epilogue ----------------
    if (MODE == 0) {
#pragma unroll
        for (int i = 0; i < 2; ++i) {
            const int rl = m0 + wm + i * 16 + g;
            const int rh = rl + 8;
#pragma unroll
            for (int j = 0; j < 8; ++j) {
                const int nl = wn + j * 8 + tg * 2;
                const int n  = n0 + nl;
                if (n < pOut) {
                    if (rl < M) {
                        float2 v;
                        v.x = fmaxf(acc[i][j][0] + biasS[nl], 0.f);
                        v.y = fmaxf(acc[i][j][1] + biasS[nl + 1], 0.f);
                        *reinterpret_cast<float2*>(&outp[(size_t)rl * pOut + n]) = v;
                    }
                    if (rh < M) {
                        float2 v;
                        v.x = fmaxf(acc[i][j][2] + biasS[nl], 0.f);
                        v.y = fmaxf(acc[i][j][3] + biasS[nl + 1], 0.f);
                        *reinterpret_cast<float2*>(&outp[(size_t)rh * pOut + n]) = v;
                    }
                }
            }
        }
    } else {
#pragma unroll
        for (int i = 0; i < 2; ++i) {
#pragma unroll
            for (int half = 0; half < 2; ++half) {
                const int r = m0 + wm + i * 16 + g + half * 8;
                const bool rv = (r < M);
                int s_ = 0, d_ = 0;
                if (rv) {
                    if (MODE == 1) { s_ = idx0[r]; d_ = idx1[r]; }
                    else           { d_ = idx0[r]; }
                }
#pragma unroll
                for (int j = 0; j < 8; ++j) {
                    const int nl = wn + j * 8 + tg * 2;
                    float v0 = acc[i][j][half * 2 + 0] + biasS[nl];
                    float v1 = acc[i][j][half * 2 + 1] + biasS[nl + 1];
                    // repack: lane gets partner (tg^1)'s pair -> contiguous float4
                    float o0 = __shfl_xor_sync(0xffffffffu, v0, 1);
                    float o1 = __shfl_xor_sync(0xffffffffu, v1, 1);
                    if ((tg & 1) == 0) {
                        const int n4 = n0 + wn + j * 8 + tg * 2;
                        if (rv && n4 < pOut) {
                            float a0 = v0, a1 = v1, a2 = o0, a3 = o1;
                            if (MODE == 1) {
                                const float4 xr = *reinterpret_cast<const float4*>(
                                    xg + (size_t)s_ * PP + n4);
                                a0 += xr.x; a1 += xr.y; a2 += xr.z; a3 += xr.w;
                            }
                            a0 = fmaxf(a0, 0.f); a1 = fmaxf(a1, 0.f);
                            a2 = fmaxf(a2, 0.f); a3 = fmaxf(a3, 0.f);
                            red4(outp + (size_t)d_ * pOut + n4, a0, a1, a2, a3);
                        }
                    }
                }
            }
        }
    }
}

// ---------------- head: g -> relu(g@Wl+bl) -> @Wl2+bl2 -> abs ----------------
__global__ void final_kernel(const float* __restrict__ g,
                             const float* __restrict__ Wl, const float* __restrict__ bl,
                             const float* __restrict__ Wl2, const float* __restrict__ bl2,
                             float* __restrict__ out)
{
    __shared__ float sg[200];
    __shared__ float s2[50];
    const int b = blockIdx.x;
    for (int i = threadIdx.x; i < 200; i += blockDim.x) sg[i] = g[(size_t)b * 200 + i];
    __syncthreads();
    if (threadIdx.x < 50) {
        float acc = bl[threadIdx.x];
        for (int k = 0; k < 200; ++k) acc = fmaf(sg[k], Wl[(size_t)k * 50 + threadIdx.x], acc);
        s2[threadIdx.x] = fmaxf(acc, 0.f);
    }
    __syncthreads();
    if (threadIdx.x == 0) {
        float o = bl2[0];
        for (int k = 0; k < 50; ++k) o = fmaf(s2[k], Wl2[k], o);
        out[b] = fabsf(o);
    }
}

// ---------------- launch ----------------
extern "C" void kernel_launch(void* const* d_in, const int* in_sizes, int n_in,
                              void* d_out, int out_size)
{
    const float* x    = (const float*)d_in[0];
    const int*   ei   = (const int*)  d_in[1];
    const float* ea   = (const float*)d_in[3];
    const int*   batch= (const int*)  d_in[4];
    const float* We1  = (const float*)d_in[5];
    const float* be1  = (const float*)d_in[6];
    const float* W1a  = (const float*)d_in[7];
    const float* b1a  = (const float*)d_in[8];
    const float* W1b  = (const float*)d_in[9];
    const float* b1b  = (const float*)d_in[10];
    const float* We2  = (const float*)d_in[11];
    const float* be2  = (const float*)d_in[12];
    const float* W2a  = (const float*)d_in[13];
    const float* b2a  = (const float*)d_in[14];
    const float* W2b  = (const float*)d_in[15];
    const float* b2b  = (const float*)d_in[16];
    const float* Wl   = (const float*)d_in[17];
    const float* bl   = (const float*)d_in[18];
    const float* Wl2  = (const float*)d_in[19];
    const float* bl2  = (const float*)d_in[20];

    const int* src = ei;
    const int* dst = ei + NE;

    float *xp, *agg, *tt, *h1, *gp;
    cudaGetSymbolAddress((void**)&xp,  g_xp);
    cudaGetSymbolAddress((void**)&agg, g_agg);
    cudaGetSymbolAddress((void**)&tt,  g_t);
    cudaGetSymbolAddress((void**)&h1,  g_h1);
    cudaGetSymbolAddress((void**)&gp,  g_gp);

    cudaFuncSetAttribute(gemm_fsp<0, PP>, cudaFuncAttributeMaxDynamicSharedMemorySize, SM_ALL);
    cudaFuncSetAttribute(gemm_fsp<1, DD>, cudaFuncAttributeMaxDynamicSharedMemorySize, SM_ALL);
    cudaFuncSetAttribute(gemm_fsp<2, PP>, cudaFuncAttributeMaxDynamicSharedMemorySize, SM_ALL);

    const int nodeBlocks = (NN + MT - 1) / MT;   // 196
    const int edgeBlocks = NE / MT;              // 3125

    // pad x (gather source for layer-1 messages)
    pad_plain_kernel<<<(NN * PP + 255) / 256, 256>>>(xp, x, NN, DD);

    // ---- layer 1 ----
    cudaMemsetAsync(agg, 0, sizeof(float) * (size_t)NN * PP);
    gemm_fsp<1, DD><<<dim3(edgeBlocks, 1), THR, SM_ALL>>>(ea, nullptr, We1, be1,
                                                          NE, DD, DD, src, dst, xp, agg, PP);
    gemm_fsp<0, PP><<<dim3(nodeBlocks, 1), THR, SM_ALL>>>(xp, agg, W1a, b1a,
                                                          NN, DD, DD, nullptr, nullptr,
                                                          nullptr, tt, PP);
    gemm_fsp<0, PP><<<dim3(nodeBlocks, 1), THR, SM_ALL>>>(tt, nullptr, W1b, b1b,
                                                          NN, DD, DD, nullptr, nullptr,
                                                          nullptr, h1, PP);

    // ---- layer 2 ----
    cudaMemsetAsync(agg, 0, sizeof(float) * (size_t)NN * PP);
    gemm_fsp<1, DD><<<dim3(edgeBlocks, 1), THR, SM_ALL>>>(ea, nullptr, We2, be2,
                                                          NE, DD, DD, src, dst, h1, agg, PP);
    gemm_fsp<0, PP><<<dim3(nodeBlocks, 1), THR, SM_ALL>>>(h1, agg, W2a, b2a,
                                                          NN, 100, DD, nullptr, nullptr,
                                                          nullptr, tt, PP);
    cudaMemsetAsync(gp, 0, sizeof(float) * NG * 200);
    gemm_fsp<2, PP><<<dim3(nodeBlocks, 2), THR, SM_ALL>>>(tt, nullptr, W2b, b2b,
                                                          NN, 200, 100, batch, nullptr,
                                                          nullptr, gp, 200);

    // ---- head ----
    final_kernel<<<NG, 64>>>(gp, Wl, bl, Wl2, bl2, (float*)d_out);
}

// round 15
// speedup vs baseline: 1.1630x; 1.1630x over previous
#include <cuda_runtime.h>
#include <cuda_bf16.h>
#include <cstdint>
#include <cstddef>

#define NN   50000
#define NNP  50048      // padded rows (multiple of 128)
#define NE   800000
#define NG   512
#define DD   101
#define PP   104        // plain fp32 pitch (16B-aligned rows: 104*4=416)
#define RS   112        // split region size (bf16 cols per half; 7 k16-tiles)
#define PA   224        // split bf16 pitch = 2*RS (448B rows, 16B aligned)
#define NKT  21         // logical k16 tiles = 3 regions * 7

// smem partition (bytes): 4-stage A pipeline + weight cache + bias
#define SM_AS   24576              // uint32 As[4][128][12]
#define SM_WC   60928              // uint32 Wc[2][56][136]
#define SM_ALL  (SM_AS + SM_WC + 512)

// ---------------- scratch (device globals; zero-initialized; no allocation) ------
__device__ __nv_bfloat16 g_ea2[(size_t)NE * PA];   // edge_attr split [hi|lo] bf16
__device__ __nv_bfloat16 g_as [(size_t)NNP * PA];  // node GEMM input split
__device__ __nv_bfloat16 g_as2[(size_t)NNP * PA];  // node GEMM intermediate split
__device__ float g_xp [(size_t)NNP * PP];          // x padded, plain fp32
__device__ float g_agg[(size_t)NNP * PP];          // scatter-add target
__device__ float g_h1 [(size_t)NNP * PP];          // layer-1 output (plain)
__device__ float g_gp [NG * 200];                  // pooled per-graph features

// ---------------- helpers ----------------
__device__ __forceinline__ void red4(float* p, float a, float b, float c, float d) {
    asm volatile("red.global.add.v4.f32 [%0], {%1,%2,%3,%4};"
                 :: "l"(p), "f"(a), "f"(b), "f"(c), "f"(d) : "memory");
}

__device__ __forceinline__ uint32_t packbf(float e, float o) {
    __nv_bfloat162 t = __floats2bfloat162_rn(e, o);   // e -> low 16 bits (k even)
    return *reinterpret_cast<uint32_t*>(&t);
}

// split pair (v0,v1) into bf16 hi-pair and lo-pair (packed u32 each)
__device__ __forceinline__ void bsplit2(float v0, float v1, uint32_t& hi, uint32_t& lo) {
    float h0 = __bfloat162float(__float2bfloat16(v0));
    float h1 = __bfloat162float(__float2bfloat16(v1));
    hi = packbf(h0, h1);
    lo = packbf(v0 - h0, v1 - h1);
}

__device__ __forceinline__ void mma16816(float c[4],
                                         uint32_t a0, uint32_t a1, uint32_t a2, uint32_t a3,
                                         uint32_t b0, uint32_t b1) {
    asm volatile(
        "mma.sync.aligned.m16n8k16.row.col.f32.bf16.bf16.f32 "
        "{%0,%1,%2,%3}, {%4,%5,%6,%7}, {%8,%9}, {%0,%1,%2,%3};"
        : "+f"(c[0]), "+f"(c[1]), "+f"(c[2]), "+f"(c[3])
        : "r"(a0), "r"(a1), "r"(a2), "r"(a3), "r"(b0), "r"(b1));
}

// ---------------- prep kernels ----------------
// plain pad: src [rows x srcPitch] -> dst [rows x PP] fp32 (zeros in pad cols)
__global__ void pad_plain_kernel(float* __restrict__ dst, const float* __restrict__ src,
                                 int rows, int srcPitch) {
    int t = blockIdx.x * blockDim.x + threadIdx.x;
    if (t < rows * PP) {
        int r = t / PP;
        int c = t - r * PP;
        dst[t] = (c < srcPitch) ? __ldg(&src[(size_t)r * srcPitch + c]) : 0.f;
    }
}

// split: src plain [rows x srcPitch] fp32 -> dst [rows x PA] bf16 [hi(112)|lo(112)]
__global__ void split_pair_kernel(__nv_bfloat16* __restrict__ dst,
                                  const float* __restrict__ src,
                                  int rows, int srcPitch) {
    long long t = (long long)blockIdx.x * blockDim.x + threadIdx.x;
    if (t >= (long long)rows * 56) return;
    int r  = (int)(t / 56);
    int c2 = (int)(t % 56) * 2;
    float v0 = (c2     < srcPitch) ? __ldg(&src[(size_t)r * srcPitch + c2    ]) : 0.f;
    float v1 = (c2 + 1 < srcPitch) ? __ldg(&src[(size_t)r * srcPitch + c2 + 1]) : 0.f;
    uint32_t hi, lo;
    bsplit2(v0, v1, hi, lo);
    uint32_t* d32 = reinterpret_cast<uint32_t*>(dst + (size_t)r * PA);
    d32[c2 / 2]      = hi;
    d32[56 + c2 / 2] = lo;
}

// dst = split(a + b), a/b plain [NN x PP]
__global__ void add_split_kernel(__nv_bfloat16* __restrict__ dst,
                                 const float* __restrict__ a,
                                 const float* __restrict__ b) {
    long long t = (long long)blockIdx.x * blockDim.x + threadIdx.x;
    if (t >= (long long)NN * 56) return;
    int r  = (int)(t / 56);
    int c2 = (int)(t % 56) * 2;
    float v0 = 0.f, v1 = 0.f;
    if (c2 < PP)     v0 = a[(size_t)r * PP + c2]     + b[(size_t)r * PP + c2];
    if (c2 + 1 < PP) v1 = a[(size_t)r * PP + c2 + 1] + b[(size_t)r * PP + c2 + 1];
    uint32_t hi, lo;
    bsplit2(v0, v1, hi, lo);
    uint32_t* d32 = reinterpret_cast<uint32_t*>(dst + (size_t)r * PA);
    d32[c2 / 2]      = hi;
    d32[56 + c2 / 2] = lo;
}

// ---------------- 3xBF16 (K-expanded) tensor-core GEMM, fused epilogues ----------
// Logical K = 336 (3 regions of 112): A regions [hi|lo|hi], B regions [hi|hi|lo]
// => sum = hiA*hiB + loA*hiB + hiA*loB  (near-fp32 product accuracy)
// Block 128x128, 8 warps, warp tile 32x64. A via cp.async 4-stage pipeline;
// full weight tile (hi+lo) cached in smem once per block.
// MODE 0: outp[m][n] = relu(C+bias), plain fp32, zeros in pad cols up to pOut
// MODE 1: v = relu(C+bias+xg[idx0[m]][n]); red4 into outp[idx1[m]]  (edge message)
// MODE 2: v = relu(C+bias);                red4 into outp[idx0[m]]  (pool by batch)
// MODE 4: store relu(C+bias) directly in SPLIT bf16 layout (outp = u32*, pOut=112)
template <int MODE>
__global__ __launch_bounds__(256, 2)
void gemm_bf3(const __nv_bfloat16* __restrict__ A,   // [M x PA] split bf16
              const float* __restrict__ B,           // [Korig x N] fp32 weights
              const float* __restrict__ bias,
              int M, int N, int Korig,
              const int* __restrict__ idx0, const int* __restrict__ idx1,
              const float* __restrict__ xg,          // plain fp32 [x PP]
              float* __restrict__ outp, int pOut)
{
    extern __shared__ char sm[];
    uint32_t* AsU   = reinterpret_cast<uint32_t*>(sm);            // [4][128][12]
    uint32_t* WcU   = reinterpret_cast<uint32_t*>(sm + SM_AS);    // [2][56][136]
    float*    biasS = reinterpret_cast<float*>(sm + SM_AS + SM_WC);

    const int tid  = threadIdx.x;
    const int m0   = blockIdx.x * 128;
    const int n0   = blockIdx.y * 128;
    const int wid  = tid >> 5;
    const int lane = tid & 31;
    const int wm   = (wid >> 1) * 32;
    const int wn   = (wid & 1) * 64;
    const int g    = lane >> 2;
    const int tg   = lane & 3;

    // A cp.async mapping: 2 threads per row, 16B each (32B = 16 bf16 per row-tile)
    const int arow = tid >> 1;
    const int aoff = (tid & 1);   // 0/1 -> +0/+16 bytes

    const char* Abase = reinterpret_cast<const char*>(A) + (size_t)(m0 + arow) * (PA * 2);

    // issue A tile kt into stage st (own commit group)
    auto issueA = [&](int kt, int st) {
        int r = (kt >= 14) ? 2 : (kt >= 7 ? 1 : 0);
        int q = kt - ((r == 2) ? 14 : (r == 1 ? 7 : 0));
        int physB = ((r == 1) ? (RS * 2) : 0) + q * 32 + aoff * 16;
        uint32_t sdst = (uint32_t)__cvta_generic_to_shared(
            AsU + st * (128 * 12) + arow * 12 + aoff * 4);
        asm volatile("cp.async.cg.shared.global [%0], [%1], 16;"
                     :: "r"(sdst), "l"(Abase + physB));
        asm volatile("cp.async.commit_group;");
    };

    issueA(0, 0);   // overlap stage-0 load with weight-cache fill

    // ---- fill weight cache: hi set + lo set, packed bf16 pairs ----
    for (int it = tid; it < 56 * 128; it += 256) {
        int kp = it >> 7, n = it & 127;
        int ke = kp * 2, ko = ke + 1;
        bool nv = (n0 + n < N);
        float we = (nv && ke < Korig) ? __ldg(&B[(size_t)ke * N + n0 + n]) : 0.f;
        float wo = (nv && ko < Korig) ? __ldg(&B[(size_t)ko * N + n0 + n]) : 0.f;
        uint32_t hi, lo;
        bsplit2(we, wo, hi, lo);
        WcU[kp * 136 + n]            = hi;
        WcU[56 * 136 + kp * 136 + n] = lo;
    }
    if (tid < 128) biasS[tid] = (n0 + tid < N) ? __ldg(&bias[n0 + tid]) : 0.f;

    issueA(1, 1);
    issueA(2, 2);

    float acc[2][8][4];
#pragma unroll
    for (int i = 0; i < 2; ++i)
#pragma unroll
        for (int j = 0; j < 8; ++j)
#pragma unroll
            for (int q = 0; q < 4; ++q) acc[i][j][q] = 0.f;

    for (int kt = 0; kt < NKT; ++kt) {
        const int st = kt & 3;
        // groups committed so far: kt+3 total; wait until <=2 pending -> group kt done
        asm volatile("cp.async.wait_group 2;");
        __syncthreads();   // all warps done reading the stage being overwritten

        if (kt + 3 < NKT) issueA(kt + 3, (kt + 3) & 3);
        else              asm volatile("cp.async.commit_group;");  // keep group count

        const int r   = (kt >= 14) ? 2 : (kt >= 7 ? 1 : 0);
        const int q   = kt - ((r == 2) ? 14 : (r == 1 ? 7 : 0));
        const uint32_t* wb = WcU + ((r == 2) ? 56 * 136 : 0) + (q * 8) * 136;

        uint32_t bfr[8][2];
#pragma unroll
        for (int j = 0; j < 8; ++j) {
            const int col = wn + j * 8 + g;
            bfr[j][0] = wb[tg * 136 + col];
            bfr[j][1] = wb[(tg + 4) * 136 + col];
        }
        const uint32_t* as = AsU + st * (128 * 12);
#pragma unroll
        for (int i = 0; i < 2; ++i) {
            const int mb = wm + i * 16 + g;
            uint32_t a0 = as[mb * 12 + tg];
            uint32_t a1 = as[(mb + 8) * 12 + tg];
            uint32_t a2 = as[mb * 12 + tg + 4];
            uint32_t a3 = as[(mb + 8) * 12 + tg + 4];
#pragma unroll
            for (int j = 0; j < 8; ++j)
                mma16816(acc[i][j], a0, a1, a2, a3, bfr[j][0], bfr[j][1]);
        }
    }

    // ---------------- epilogue ----------------
    if (MODE == 0) {
#pragma unroll
        for (int i = 0; i < 2; ++i) {
            const int rl = m0 + wm + i * 16 + g;
            const int rh = rl + 8;
#pragma unroll
            for (int j = 0; j < 8; ++j) {
                const int nl = wn + j * 8 + tg * 2;
                const int n  = n0 + nl;
                if (n < pOut) {
                    if (rl < M) {
                        float2 v;
                        v.x = fmaxf(acc[i][j][0] + biasS[nl], 0.f);
                        v.y = fmaxf(acc[i][j][1] + biasS[nl + 1], 0.f);
                        *reinterpret_cast<float2*>(&outp[(size_t)rl * pOut + n]) = v;
                    }
                    if (rh < M) {
                        float2 v;
                        v.x = fmaxf(acc[i][j][2] + biasS[nl], 0.f);
                        v.y = fmaxf(acc[i][j][3] + biasS[nl + 1], 0.f);
                        *reinterpret_cast<float2*>(&outp[(size_t)rh * pOut + n]) = v;
                    }
                }
            }
        }
    } else if (MODE == 4) {
        // store relu(C+bias) in split layout: u32 row pitch pOut(=112):
        // hi pair at [nl/2], lo pair at [56 + nl/2]; nl < 112 only (grid.y==1).
        uint32_t* o32 = reinterpret_cast<uint32_t*>(outp);
#pragma unroll
        for (int i = 0; i < 2; ++i) {
            const int rl = m0 + wm + i * 16 + g;
            const int rh = rl + 8;
#pragma unroll
            for (int j = 0; j < 8; ++j) {
                const int nl = wn + j * 8 + tg * 2;
                if (nl < 112) {
                    if (rl < M) {
                        float v0 = fmaxf(acc[i][j][0] + biasS[nl], 0.f);
                        float v1 = fmaxf(acc[i][j][1] + biasS[nl + 1], 0.f);
                        uint32_t hi, lo;
                        bsplit2(v0, v1, hi, lo);
                        o32[(size_t)rl * pOut + nl / 2]      = hi;
                        o32[(size_t)rl * pOut + 56 + nl / 2] = lo;
                    }
                    if (rh < M) {
                        float v0 = fmaxf(acc[i][j][2] + biasS[nl], 0.f);
                        float v1 = fmaxf(acc[i][j][3] + biasS[nl + 1], 0.f);
                        uint32_t hi, lo;
                        bsplit2(v0, v1, hi, lo);
                        o32[(size_t)rh * pOut + nl / 2]      = hi;
                        o32[(size_t)rh * pOut + 56 + nl / 2] = lo;
                    }
                }
            }
        }
    } else {
#pragma unroll
        for (int i = 0; i < 2; ++i) {
#pragma unroll
            for (int half = 0; half < 2; ++half) {
                const int r = m0 + wm + i * 16 + g + half * 8;
                const bool rv = (r < M);
                int s_ = 0, d_ = 0;
                if (rv) {
                    if (MODE == 1) { s_ = idx0[r]; d_ = idx1[r]; }
                    else           { d_ = idx0[r]; }
                }
#pragma unroll
                for (int j = 0; j < 8; ++j) {
                    const int nl = wn + j * 8 + tg * 2;
                    float v0 = acc[i][j][half * 2 + 0] + biasS[nl];
                    float v1 = acc[i][j][half * 2 + 1] + biasS[nl + 1];
                    // repack: lane gets partner (tg^1)'s pair -> contiguous float4
                    float o0 = __shfl_xor_sync(0xffffffffu, v0, 1);
                    float o1 = __shfl_xor_sync(0xffffffffu, v1, 1);
                    if ((tg & 1) == 0) {
                        const int n4 = n0 + wn + j * 8 + tg * 2;
                        if (rv && n4 < pOut) {
                            float a0 = v0, a1 = v1, a2 = o0, a3 = o1;
                            if (MODE == 1) {
                                const float4 xr = *reinterpret_cast<const float4*>(
                                    xg + (size_t)s_ * PP + n4);
                                a0 += xr.x; a1 += xr.y; a2 += xr.z; a3 += xr.w;
                            }
                            a0 = fmaxf(a0, 0.f); a1 = fmaxf(a1, 0.f);
                            a2 = fmaxf(a2, 0.f); a3 = fmaxf(a3, 0.f);
                            red4(outp + (size_t)d_ * pOut + n4, a0, a1, a2, a3);
                        }
                    }
                }
            }
        }
    }
}

// ---------------- head: g -> relu(g@Wl+bl) -> @Wl2+bl2 -> abs ----------------
__global__ void final_kernel(const float* __restrict__ g,
                             const float* __restrict__ Wl, const float* __restrict__ bl,
                             const float* __restrict__ Wl2, const float* __restrict__ bl2,
                             float* __restrict__ out)
{
    __shared__ float sg[200];
    __shared__ float s2[50];
    const int b = blockIdx.x;
    for (int i = threadIdx.x; i < 200; i += blockDim.x) sg[i] = g[(size_t)b * 200 + i];
    __syncthreads();
    if (threadIdx.x < 50) {
        float acc = bl[threadIdx.x];
        for (int k = 0; k < 200; ++k) acc = fmaf(sg[k], Wl[(size_t)k * 50 + threadIdx.x], acc);
        s2[threadIdx.x] = fmaxf(acc, 0.f);
    }
    __syncthreads();
    if (threadIdx.x == 0) {
        float o = bl2[0];
        for (int k = 0; k < 50; ++k) o = fmaf(s2[k], Wl2[k], o);
        out[b] = fabsf(o);
    }
}

// ---------------- launch ----------------
extern "C" void kernel_launch(void* const* d_in, const int* in_sizes, int n_in,
                              void* d_out, int out_size)
{
    const float* x    = (const float*)d_in[0];
    const int*   ei   = (const int*)  d_in[1];
    const float* ea   = (const float*)d_in[3];
    const int*   batch= (const int*)  d_in[4];
    const float* We1  = (const float*)d_in[5];
    const float* be1  = (const float*)d_in[6];
    const float* W1a  = (const float*)d_in[7];
    const float* b1a  = (const float*)d_in[8];
    const float* W1b  = (const float*)d_in[9];
    const float* b1b  = (const float*)d_in[10];
    const float* We2  = (const float*)d_in[11];
    const float* be2  = (const float*)d_in[12];
    const float* W2a  = (const float*)d_in[13];
    const float* b2a  = (const float*)d_in[14];
    const float* W2b  = (const float*)d_in[15];
    const float* b2b  = (const float*)d_in[16];
    const float* Wl   = (const float*)d_in[17];
    const float* bl   = (const float*)d_in[18];
    const float* Wl2  = (const float*)d_in[19];
    const float* bl2  = (const float*)d_in[20];

    const int* src = ei;
    const int* dst = ei + NE;

    __nv_bfloat16 *ea2, *as, *as2;
    float *xp, *agg, *h1, *gp;
    cudaGetSymbolAddress((void**)&ea2, g_ea2);
    cudaGetSymbolAddress((void**)&as,  g_as);
    cudaGetSymbolAddress((void**)&as2, g_as2);
    cudaGetSymbolAddress((void**)&xp,  g_xp);
    cudaGetSymbolAddress((void**)&agg, g_agg);
    cudaGetSymbolAddress((void**)&h1,  g_h1);
    cudaGetSymbolAddress((void**)&gp,  g_gp);

    cudaFuncSetAttribute(gemm_bf3<0>, cudaFuncAttributeMaxDynamicSharedMemorySize, SM_ALL);
    cudaFuncSetAttribute(gemm_bf3<1>, cudaFuncAttributeMaxDynamicSharedMemorySize, SM_ALL);
    cudaFuncSetAttribute(gemm_bf3<2>, cudaFuncAttributeMaxDynamicSharedMemorySize, SM_ALL);
    cudaFuncSetAttribute(gemm_bf3<4>, cudaFuncAttributeMaxDynamicSharedMemorySize, SM_ALL);

    const int nodeBlocks = (NN + 127) / 128;   // 391
    const int edgeBlocks = NE / 128;           // 6250

    // ---- prep: split edge_attr (once per call), pad x plain ----
    {
        long long t = (long long)NE * 56;
        split_pair_kernel<<<(int)((t + 255) / 256), 256>>>(ea2, ea, NE, DD);
    }
    pad_plain_kernel<<<(NN * PP + 255) / 256, 256>>>(xp, x, NN, DD);

    const int nsplitBlocks = (int)(((long long)NN * 56 + 255) / 256);

    // ---- layer 1 ----
    cudaMemsetAsync(agg, 0, sizeof(float) * (size_t)NN * PP);
    gemm_bf3<1><<<dim3(edgeBlocks, 1), 256, SM_ALL>>>(ea2, We1, be1, NE, DD, DD,
                                                      src, dst, xp, agg, PP);
    add_split_kernel<<<nsplitBlocks, 256>>>(as, xp, agg);
    gemm_bf3<4><<<dim3(nodeBlocks, 1), 256, SM_ALL>>>(as, W1a, b1a, NN, DD, DD,
                                                      nullptr, nullptr, nullptr,
                                                      (float*)as2, 112);
    gemm_bf3<0><<<dim3(nodeBlocks, 1), 256, SM_ALL>>>(as2, W1b, b1b, NN, DD, DD,
                                                      nullptr, nullptr, nullptr, h1, PP);

    // ---- layer 2 ----
    cudaMemsetAsync(agg, 0, sizeof(float) * (size_t)NN * PP);
    gemm_bf3<1><<<dim3(edgeBlocks, 1), 256, SM_ALL>>>(ea2, We2, be2, NE, DD, DD,
                                                      src, dst, h1, agg, PP);
    add_split_kernel<<<nsplitBlocks, 256>>>(as, h1, agg);
    gemm_bf3<4><<<dim3(nodeBlocks, 1), 256, SM_ALL>>>(as, W2a, b2a, NN, 100, DD,
                                                      nullptr, nullptr, nullptr,
                                                      (float*)as2, 112);
    cudaMemsetAsync(gp, 0, sizeof(float) * NG * 200);
    gemm_bf3<2><<<dim3(nodeBlocks, 2), 256, SM_ALL>>>(as2, W2b, b2b, NN, 200, 100,
                                                      batch, nullptr, nullptr, gp, 200);

    // ---- head ----
    final_kernel<<<NG, 64>>>(gp, Wl, bl, Wl2, bl2, (float*)d_out);
}

// round 17
// speedup vs baseline: 1.2963x; 1.1146x over previous
#include <cuda_runtime.h>
#include <cuda_bf16.h>
#include <cstdint>
#include <cstddef>

#define NN   50000
#define NNP  50048      // padded rows (multiple of 128)
#define NE   800000
#define NG   512
#define DD   101
#define PP   104        // plain fp32 pitch (16B-aligned rows: 104*4=416)
#define RS   112        // split region size (bf16 cols per half; 7 k16-tiles)
#define PA   224        // split bf16 pitch = 2*RS (448B rows, 16B aligned)
#define NKT  21         // logical k16 tiles for bf3 kernel = 3 regions * 7

// ---- gemm_bf3 smem (bytes): 4-stage A pipeline + weight cache + bias ----
#define SM_AS   24576              // uint32 As[4][128][12]
#define SM_WC   60928              // uint32 Wc[2][56][136]
#define SM_ALL  (SM_AS + SM_WC + 512)

// ---- gemm_edge smem: fp32 A windows [4][128][20] + same weight cache ----
#define SME_AS  40960
#define SME_ALL (SME_AS + SM_WC + 512)

// ---------------- scratch (device globals; zero-initialized; no allocation) ------
__device__ __nv_bfloat16 g_as [(size_t)NNP * PA];  // node GEMM input split
__device__ __nv_bfloat16 g_as2[(size_t)NNP * PA];  // node GEMM intermediate split
__device__ float g_xp [(size_t)NNP * PP];          // x padded, plain fp32
__device__ float g_agg[(size_t)NNP * PP];          // scatter-add target
__device__ float g_h1 [(size_t)NNP * PP];          // layer-1 output (plain)
__device__ float g_gp [NG * 200];                  // pooled per-graph features

// ---------------- helpers ----------------
__device__ __forceinline__ void red4(float* p, float a, float b, float c, float d) {
    asm volatile("red.global.add.v4.f32 [%0], {%1,%2,%3,%4};"
                 :: "l"(p), "f"(a), "f"(b), "f"(c), "f"(d) : "memory");
}

__device__ __forceinline__ uint32_t packbf(float e, float o) {
    __nv_bfloat162 t = __floats2bfloat162_rn(e, o);   // e -> low 16 bits (k even)
    return *reinterpret_cast<uint32_t*>(&t);
}

// split pair (v0,v1) into bf16 hi-pair and lo-pair (packed u32 each)
__device__ __forceinline__ void bsplit2(float v0, float v1, uint32_t& hi, uint32_t& lo) {
    float h0 = __bfloat162float(__float2bfloat16(v0));
    float h1 = __bfloat162float(__float2bfloat16(v1));
    hi = packbf(h0, h1);
    lo = packbf(v0 - h0, v1 - h1);
}

__device__ __forceinline__ void mma16816(float c[4],
                                         uint32_t a0, uint32_t a1, uint32_t a2, uint32_t a3,
                                         uint32_t b0, uint32_t b1) {
    asm volatile(
        "mma.sync.aligned.m16n8k16.row.col.f32.bf16.bf16.f32 "
        "{%0,%1,%2,%3}, {%4,%5,%6,%7}, {%8,%9}, {%0,%1,%2,%3};"
        : "+f"(c[0]), "+f"(c[1]), "+f"(c[2]), "+f"(c[3])
        : "r"(a0), "r"(a1), "r"(a2), "r"(a3), "r"(b0), "r"(b1));
}

// ---------------- prep kernels ----------------
__global__ void pad_plain_kernel(float* __restrict__ dst, const float* __restrict__ src,
                                 int rows, int srcPitch) {
    int t = blockIdx.x * blockDim.x + threadIdx.x;
    if (t < rows * PP) {
        int r = t / PP;
        int c = t - r * PP;
        dst[t] = (c < srcPitch) ? __ldg(&src[(size_t)r * srcPitch + c]) : 0.f;
    }
}

// dst = split(a + b), a/b plain [NN x PP]
__global__ void add_split_kernel(__nv_bfloat16* __restrict__ dst,
                                 const float* __restrict__ a,
                                 const float* __restrict__ b) {
    long long t = (long long)blockIdx.x * blockDim.x + threadIdx.x;
    if (t >= (long long)NN * 56) return;
    int r  = (int)(t / 56);
    int c2 = (int)(t % 56) * 2;
    float v0 = 0.f, v1 = 0.f;
    if (c2 < PP)     v0 = a[(size_t)r * PP + c2]     + b[(size_t)r * PP + c2];
    if (c2 + 1 < PP) v1 = a[(size_t)r * PP + c2 + 1] + b[(size_t)r * PP + c2 + 1];
    uint32_t hi, lo;
    bsplit2(v0, v1, hi, lo);
    uint32_t* d32 = reinterpret_cast<uint32_t*>(dst + (size_t)r * PA);
    d32[c2 / 2]      = hi;
    d32[56 + c2 / 2] = lo;
}

// ============ EDGE kernel: raw fp32 A + in-register bf16 split + scatter =========
// A: raw fp32 [M x 101], rows NOT 16B aligned. Per row the k16 window [k0,k0+16)
// is fetched as a 20-float window aligned down by sh = row&3 (101 = 1 mod 4, k0 =
// 0 mod 4 -> (101*row + k0) mod 4 == row mod 4). 4-stage cp.async pipeline.
// Per physical k-tile (7 total): build hiA/loA frags by converting fp32 in regs,
// run hiA*hiB + loA*hiB + hiA*loB against the smem-cached hi/lo weight planes.
// Epilogue: v = relu(C + bias + xg[src[m]]); red4 into outp[dst[m]].
__global__ __launch_bounds__(256, 2)
void gemm_edge(const float* __restrict__ A,
               const float* __restrict__ B,
               const float* __restrict__ bias,
               int M, int N, int Korig,
               const int* __restrict__ idx0, const int* __restrict__ idx1,
               const float* __restrict__ xg,
               float* __restrict__ outp, int pOut)
{
    extern __shared__ char sm[];
    float*    AsF   = reinterpret_cast<float*>(sm);               // [4][128][20]
    uint32_t* WcU   = reinterpret_cast<uint32_t*>(sm + SME_AS);   // [2][56][136]
    float*    biasS = reinterpret_cast<float*>(sm + SME_AS + SM_WC);

    const int tid  = threadIdx.x;
    const int m0   = blockIdx.x * 128;
    const int wid  = tid >> 5;
    const int lane = tid & 31;
    const int wm   = (wid >> 1) * 32;
    const int wn   = (wid & 1) * 64;
    const int g    = lane >> 2;
    const int tg   = lane & 3;

    // A load mapping: 2 threads per row; thread0 chunks {0,1,2}, thread1 {3,4}
    const int arow = tid >> 1;
    const int ach  = (tid & 1);
    const long rg  = m0 + arow;           // global row
    const int  sh  = (int)(rg & 3);       // alignment shift (fp32 units)
    const bool lastblk = (m0 + 128 >= M);
    const char* aend = reinterpret_cast<const char*>(A + (size_t)M * DD);

    auto issueA = [&](int kt, int st) {
        const char* srcb = reinterpret_cast<const char*>(A + (DD * rg + kt * 16 - sh));
        float* dstf = AsF + st * (128 * 20) + arow * 20;
        const int c0 = ach ? 3 : 0;
        const int cn = ach ? 2 : 3;
#pragma unroll
        for (int c = 0; c < 3; ++c) {
            if (c >= cn) break;
            const char* s = srcb + (c0 + c) * 16;
            uint32_t d = (uint32_t)__cvta_generic_to_shared(dstf + (c0 + c) * 4);
            int sz = 16;
            if (lastblk) {
                long rem = (long)(aend - s);
                sz = (rem >= 16) ? 16 : (rem > 0 ? ((int)rem & ~3) : 0);
            }
            asm volatile("cp.async.cg.shared.global [%0], [%1], 16, %2;"
                         :: "r"(d), "l"(s), "r"(sz));
        }
        asm volatile("cp.async.commit_group;");
    };

    issueA(0, 0);

    // ---- weight cache: hi plane + lo plane ----
    for (int it = tid; it < 56 * 128; it += 256) {
        int kp = it >> 7, n = it & 127;
        int ke = kp * 2, ko = ke + 1;
        bool nv = (n < N);
        float we = (nv && ke < Korig) ? __ldg(&B[(size_t)ke * N + n]) : 0.f;
        float wo = (nv && ko < Korig) ? __ldg(&B[(size_t)ko * N + n]) : 0.f;
        uint32_t hi, lo;
        bsplit2(we, wo, hi, lo);
        WcU[kp * 136 + n]            = hi;
        WcU[56 * 136 + kp * 136 + n] = lo;
    }
    if (tid < 128) biasS[tid] = (tid < N) ? __ldg(&bias[tid]) : 0.f;

    issueA(1, 1);
    issueA(2, 2);

    float acc[2][8][4];
#pragma unroll
    for (int i = 0; i < 2; ++i)
#pragma unroll
        for (int j = 0; j < 8; ++j)
#pragma unroll
            for (int q = 0; q < 4; ++q) acc[i][j][q] = 0.f;

    for (int kt = 0; kt < 7; ++kt) {
        const int st = kt & 3;
        asm volatile("cp.async.wait_group 2;");
        __syncthreads();
        if (kt + 3 < 7) issueA(kt + 3, (kt + 3) & 3);
        else            asm volatile("cp.async.commit_group;");

        const bool tail = (kt == 6);
        const float* as = AsF + st * (128 * 20);

        // ---- build A fragments (hi + lo) with in-register split ----
        uint32_t ah[2][4], al[2][4];
#pragma unroll
        for (int i = 0; i < 2; ++i) {
            const float* p0 = as + (wm + i * 16 + g) * 20 + (g & 3);
            const float* p1 = p0 + 8 * 20;
            float f00 = p0[2 * tg], f01 = p0[2 * tg + 1];
            float f02 = p0[2 * tg + 8], f03 = p0[2 * tg + 9];
            float f10 = p1[2 * tg], f11 = p1[2 * tg + 1];
            float f12 = p1[2 * tg + 8], f13 = p1[2 * tg + 9];
            if (tail) {                    // global k = 96 + kl, valid kl <= 4
                if (tg > 2) f00 = 0.f;
                if (tg > 1) f01 = 0.f;
                f02 = 0.f; f03 = 0.f;
                if (tg > 2) f10 = 0.f;
                if (tg > 1) f11 = 0.f;
                f12 = 0.f; f13 = 0.f;
            }
            bsplit2(f00, f01, ah[i][0], al[i][0]);
            bsplit2(f10, f11, ah[i][1], al[i][1]);
            bsplit2(f02, f03, ah[i][2], al[i][2]);
            bsplit2(f12, f13, ah[i][3], al[i][3]);
        }

        // ---- 3 compensated passes fused per j: hi*hi, lo*hi, hi*lo ----
        const uint32_t* wbh = WcU + (kt * 8) * 136;
        const uint32_t* wbl = WcU + 56 * 136 + (kt * 8) * 136;
#pragma unroll
        for (int j = 0; j < 8; ++j) {
            const int col = wn + j * 8 + g;
            uint32_t b0 = wbh[tg * 136 + col];
            uint32_t b1 = wbh[(tg + 4) * 136 + col];
            mma16816(acc[0][j], ah[0][0], ah[0][1], ah[0][2], ah[0][3], b0, b1);
            mma16816(acc[1][j], ah[1][0], ah[1][1], ah[1][2], ah[1][3], b0, b1);
            mma16816(acc[0][j], al[0][0], al[0][1], al[0][2], al[0][3], b0, b1);
            mma16816(acc[1][j], al[1][0], al[1][1], al[1][2], al[1][3], b0, b1);
            uint32_t c0 = wbl[tg * 136 + col];
            uint32_t c1 = wbl[(tg + 4) * 136 + col];
            mma16816(acc[0][j], ah[0][0], ah[0][1], ah[0][2], ah[0][3], c0, c1);
            mma16816(acc[1][j], ah[1][0], ah[1][1], ah[1][2], ah[1][3], c0, c1);
        }
    }

    // ---- epilogue: gather + relu + vector scatter-add ----
#pragma unroll
    for (int i = 0; i < 2; ++i) {
#pragma unroll
        for (int half = 0; half < 2; ++half) {
            const int r = m0 + wm + i * 16 + g + half * 8;
            const bool rv = (r < M);
            int s_ = 0, d_ = 0;
            if (rv) { s_ = idx0[r]; d_ = idx1[r]; }
#pragma unroll
            for (int j = 0; j < 8; ++j) {
                const int nl = wn + j * 8 + tg * 2;
                float v0 = acc[i][j][half * 2 + 0] + biasS[nl];
                float v1 = acc[i][j][half * 2 + 1] + biasS[nl + 1];
                float o0 = __shfl_xor_sync(0xffffffffu, v0, 1);
                float o1 = __shfl_xor_sync(0xffffffffu, v1, 1);
                if ((tg & 1) == 0) {
                    const int n4 = wn + j * 8 + tg * 2;
                    if (rv && n4 < pOut) {
                        const float4 xr = *reinterpret_cast<const float4*>(
                            xg + (size_t)s_ * PP + n4);
                        float a0 = fmaxf(v0 + xr.x, 0.f);
                        float a1 = fmaxf(v1 + xr.y, 0.f);
                        float a2 = fmaxf(o0 + xr.z, 0.f);
                        float a3 = fmaxf(o1 + xr.w, 0.f);
                        red4(outp + (size_t)d_ * pOut + n4, a0, a1, a2, a3);
                    }
                }
            }
        }
    }
}

// ---------------- node GEMM: split bf16 A (proven R15 kernel) ----------------
// MODE 0: plain fp32 relu store; MODE 2: pool red4 by batch; MODE 4: split store
template <int MODE>
__global__ __launch_bounds__(256, 2)
void gemm_bf3(const __nv_bfloat16* __restrict__ A,
              const float* __restrict__ B,
              const float* __restrict__ bias,
              int M, int N, int Korig,
              const int* __restrict__ idx0,
              float* __restrict__ outp, int pOut)
{
    extern __shared__ char sm[];
    uint32_t* AsU   = reinterpret_cast<uint32_t*>(sm);            // [4][128][12]
    uint32_t* WcU   = reinterpret_cast<uint32_t*>(sm + SM_AS);    // [2][56][136]
    float*    biasS = reinterpret_cast<float*>(sm + SM_AS + SM_WC);

    const int tid  = threadIdx.x;
    const int m0   = blockIdx.x * 128;
    const int n0   = blockIdx.y * 128;
    const int wid  = tid >> 5;
    const int lane = tid & 31;
    const int wm   = (wid >> 1) * 32;
    const int wn   = (wid & 1) * 64;
    const int g    = lane >> 2;
    const int tg   = lane & 3;

    const int arow = tid >> 1;
    const int aoff = (tid & 1);

    const char* Abase = reinterpret_cast<const char*>(A) + (size_t)(m0 + arow) * (PA * 2);

    auto issueA = [&](int kt, int st) {
        int r = (kt >= 14) ? 2 : (kt >= 7 ? 1 : 0);
        int q = kt - ((r == 2) ? 14 : (r == 1 ? 7 : 0));
        int physB = ((r == 1) ? (RS * 2) : 0) + q * 32 + aoff * 16;
        uint32_t sdst = (uint32_t)__cvta_generic_to_shared(
            AsU + st * (128 * 12) + arow * 12 + aoff * 4);
        asm volatile("cp.async.cg.shared.global [%0], [%1], 16;"
                     :: "r"(sdst), "l"(Abase + physB));
        asm volatile("cp.async.commit_group;");
    };

    issueA(0, 0);

    for (int it = tid; it < 56 * 128; it += 256) {
        int kp = it >> 7, n = it & 127;
        int ke = kp * 2, ko = ke + 1;
        bool nv = (n0 + n < N);
        float we = (nv && ke < Korig) ? __ldg(&B[(size_t)ke * N + n0 + n]) : 0.f;
        float wo = (nv && ko < Korig) ? __ldg(&B[(size_t)ko * N + n0 + n]) : 0.f;
        uint32_t hi, lo;
        bsplit2(we, wo, hi, lo);
        WcU[kp * 136 + n]            = hi;
        WcU[56 * 136 + kp * 136 + n] = lo;
    }
    if (tid < 128) biasS[tid] = (n0 + tid < N) ? __ldg(&bias[n0 + tid]) : 0.f;

    issueA(1, 1);
    issueA(2, 2);

    float acc[2][8][4];
#pragma unroll
    for (int i = 0; i < 2; ++i)
#pragma unroll
        for (int j = 0; j < 8; ++j)
#pragma unroll
            for (int q = 0; q < 4; ++q) acc[i][j][q] = 0.f;

    for (int kt = 0; kt < NKT; ++kt) {
        const int st = kt & 3;
        asm volatile("cp.async.wait_group 2;");
        __syncthreads();

        if (kt + 3 < NKT) issueA(kt + 3, (kt + 3) & 3);
        else              asm volatile("cp.async.commit_group;");

        const int r   = (kt >= 14) ? 2 : (kt >= 7 ? 1 : 0);
        const int q   = kt - ((r == 2) ? 14 : (r == 1 ? 7 : 0));
        const uint32_t* wb = WcU + ((r == 2) ? 56 * 136 : 0) + (q * 8) * 136;

        uint32_t bfr[8][2];
#pragma unroll
        for (int j = 0; j < 8; ++j) {
            const int col = wn + j * 8 + g;
            bfr[j][0] = wb[tg * 136 + col];
            bfr[j][1] = wb[(tg + 4) * 136 + col];
        }
        const uint32_t* as = AsU + st * (128 * 12);
#pragma unroll
        for (int i = 0; i < 2; ++i) {
            const int mb = wm + i * 16 + g;
            uint32_t a0 = as[mb * 12 + tg];
            uint32_t a1 = as[(mb + 8) * 12 + tg];
            uint32_t a2 = as[mb * 12 + tg + 4];
            uint32_t a3 = as[(mb + 8) * 12 + tg + 4];
#pragma unroll
            for (int j = 0; j < 8; ++j)
                mma16816(acc[i][j], a0, a1, a2, a3, bfr[j][0], bfr[j][1]);
        }
    }

    if (MODE == 0) {
#pragma unroll
        for (int i = 0; i < 2; ++i) {
            const int rl = m0 + wm + i * 16 + g;
            const int rh = rl + 8;
#pragma unroll
            for (int j = 0; j < 8; ++j) {
                const int nl = wn + j * 8 + tg * 2;
                const int n  = n0 + nl;
                if (n < pOut) {
                    if (rl < M) {
                        float2 v;
                        v.x = fmaxf(acc[i][j][0] + biasS[nl], 0.f);
                        v.y = fmaxf(acc[i][j][1] + biasS[nl + 1], 0.f);
                        *reinterpret_cast<float2*>(&outp[(size_t)rl * pOut + n]) = v;
                    }
                    if (rh < M) {
                        float2 v;
                        v.x = fmaxf(acc[i][j][2] + biasS[nl], 0.f);
                        v.y = fmaxf(acc[i][j][3] + biasS[nl + 1], 0.f);
                        *reinterpret_cast<float2*>(&outp[(size_t)rh * pOut + n]) = v;
                    }
                }
            }
        }
    } else if (MODE == 4) {
        uint32_t* o32 = reinterpret_cast<uint32_t*>(outp);
#pragma unroll
        for (int i = 0; i < 2; ++i) {
            const int rl = m0 + wm + i * 16 + g;
            const int rh = rl + 8;
#pragma unroll
            for (int j = 0; j < 8; ++j) {
                const int nl = wn + j * 8 + tg * 2;
                if (nl < 112) {
                    if (rl < M) {
                        float v0 = fmaxf(acc[i][j][0] + biasS[nl], 0.f);
                        float v1 = fmaxf(acc[i][j][1] + biasS[nl + 1], 0.f);
                        uint32_t hi, lo;
                        bsplit2(v0, v1, hi, lo);
                        o32[(size_t)rl * pOut + nl / 2]      = hi;
                        o32[(size_t)rl * pOut + 56 + nl / 2] = lo;
                    }
                    if (rh < M) {
                        float v0 = fmaxf(acc[i][j][2] + biasS[nl], 0.f);
                        float v1 = fmaxf(acc[i][j][3] + biasS[nl + 1], 0.f);
                        uint32_t hi, lo;
                        bsplit2(v0, v1, hi, lo);
                        o32[(size_t)rh * pOut + nl / 2]      = hi;
                        o32[(size_t)rh * pOut + 56 + nl / 2] = lo;
                    }
                }
            }
        }
    } else {   // MODE 2: pool by batch
#pragma unroll
        for (int i = 0; i < 2; ++i) {
#pragma unroll
            for (int half = 0; half < 2; ++half) {
                const int r = m0 + wm + i * 16 + g + half * 8;
                const bool rv = (r < M);
                int d_ = 0;
                if (rv) d_ = idx0[r];
#pragma unroll
                for (int j = 0; j < 8; ++j) {
                    const int nl = wn + j * 8 + tg * 2;
                    float v0 = acc[i][j][half * 2 + 0] + biasS[nl];
                    float v1 = acc[i][j][half * 2 + 1] + biasS[nl + 1];
                    float o0 = __shfl_xor_sync(0xffffffffu, v0, 1);
                    float o1 = __shfl_xor_sync(0xffffffffu, v1, 1);
                    if ((tg & 1) == 0) {
                        const int n4 = n0 + wn + j * 8 + tg * 2;
                        if (rv && n4 < pOut) {
                            float a0 = fmaxf(v0, 0.f), a1 = fmaxf(v1, 0.f);
                            float a2 = fmaxf(o0, 0.f), a3 = fmaxf(o1, 0.f);
                            red4(outp + (size_t)d_ * pOut + n4, a0, a1, a2, a3);
                        }
                    }
                }
            }
        }
    }
}

// ---------------- head ----------------
__global__ void final_kernel(const float* __restrict__ g,
                             const float* __restrict__ Wl, const float* __restrict__ bl,
                             const float* __restrict__ Wl2, const float* __restrict__ bl2,
                             float* __restrict__ out)
{
    __shared__ float sg[200];
    __shared__ float s2[50];
    const int b = blockIdx.x;
    for (int i = threadIdx.x; i < 200; i += blockDim.x) sg[i] = g[(size_t)b * 200 + i];
    __syncthreads();
    if (threadIdx.x < 50) {
        float acc = bl[threadIdx.x];
        for (int k = 0; k < 200; ++k) acc = fmaf(sg[k], Wl[(size_t)k * 50 + threadIdx.x], acc);
        s2[threadIdx.x] = fmaxf(acc, 0.f);
    }
    __syncthreads();
    if (threadIdx.x == 0) {
        float o = bl2[0];
        for (int k = 0; k < 50; ++k) o = fmaf(s2[k], Wl2[k], o);
        out[b] = fabsf(o);
    }
}

// ---------------- launch ----------------
extern "C" void kernel_launch(void* const* d_in, const int* in_sizes, int n_in,
                              void* d_out, int out_size)
{
    const float* x    = (const float*)d_in[0];
    const int*   ei   = (const int*)  d_in[1];
    const float* ea   = (const float*)d_in[3];
    const int*   batch= (const int*)  d_in[4];
    const float* We1  = (const float*)d_in[5];
    const float* be1  = (const float*)d_in[6];
    const float* W1a  = (const float*)d_in[7];
    const float* b1a  = (const float*)d_in[8];
    const float* W1b  = (const float*)d_in[9];
    const float* b1b  = (const float*)d_in[10];
    const float* We2  = (const float*)d_in[11];
    const float* be2  = (const float*)d_in[12];
    const float* W2a  = (const float*)d_in[13];
    const float* b2a  = (const float*)d_in[14];
    const float* W2b  = (const float*)d_in[15];
    const float* b2b  = (const float*)d_in[16];
    const float* Wl   = (const float*)d_in[17];
    const float* bl   = (const float*)d_in[18];
    const float* Wl2  = (const float*)d_in[19];
    const float* bl2  = (const float*)d_in[20];

    const int* src = ei;
    const int* dst = ei + NE;

    __nv_bfloat16 *as, *as2;
    float *xp, *agg, *h1, *gp;
    cudaGetSymbolAddress((void**)&as,  g_as);
    cudaGetSymbolAddress((void**)&as2, g_as2);
    cudaGetSymbolAddress((void**)&xp,  g_xp);
    cudaGetSymbolAddress((void**)&agg, g_agg);
    cudaGetSymbolAddress((void**)&h1,  g_h1);
    cudaGetSymbolAddress((void**)&gp,  g_gp);

    cudaFuncSetAttribute(gemm_edge,   cudaFuncAttributeMaxDynamicSharedMemorySize, SME_ALL);
    cudaFuncSetAttribute(gemm_bf3<0>, cudaFuncAttributeMaxDynamicSharedMemorySize, SM_ALL);
    cudaFuncSetAttribute(gemm_bf3<2>, cudaFuncAttributeMaxDynamicSharedMemorySize, SM_ALL);
    cudaFuncSetAttribute(gemm_bf3<4>, cudaFuncAttributeMaxDynamicSharedMemorySize, SM_ALL);

    const int nodeBlocks = (NN + 127) / 128;   // 391
    const int edgeBlocks = NE / 128;           // 6250
    const int nsplitBlocks = (int)(((long long)NN * 56 + 255) / 256);

    pad_plain_kernel<<<(NN * PP + 255) / 256, 256>>>(xp, x, NN, DD);

    // ---- layer 1 ----
    cudaMemsetAsync(agg, 0, sizeof(float) * (size_t)NN * PP);
    gemm_edge<<<dim3(edgeBlocks, 1), 256, SME_ALL>>>(ea, We1, be1, NE, DD, DD,
                                                     src, dst, xp, agg, PP);
    add_split_kernel<<<nsplitBlocks, 256>>>(as, xp, agg);
    gemm_bf3<4><<<dim3(nodeBlocks, 1), 256, SM_ALL>>>(as, W1a, b1a, NN, DD, DD,
                                                      nullptr, (float*)as2, 112);
    gemm_bf3<0><<<dim3(nodeBlocks, 1), 256, SM_ALL>>>(as2, W1b, b1b, NN, DD, DD,
                                                      nullptr, h1, PP);

    // ---- layer 2 ----
    cudaMemsetAsync(agg, 0, sizeof(float) * (size_t)NN * PP);
    gemm_edge<<<dim3(edgeBlocks, 1), 256, SME_ALL>>>(ea, We2, be2, NE, DD, DD,
                                                     src, dst, h1, agg, PP);
    add_split_kernel<<<nsplitBlocks, 256>>>(as, h1, agg);
    gemm_bf3<4><<<dim3(nodeBlocks, 1), 256, SM_ALL>>>(as, W2a, b2a, NN, 100, DD,
                                                      nullptr, (float*)as2, 112);
    cudaMemsetAsync(gp, 0, sizeof(float) * NG * 200);
    gemm_bf3<2><<<dim3(nodeBlocks, 2), 256, SM_ALL>>>(as2, W2b, b2b, NN, 200, 100,
                                                      batch, gp, 200);

    // ---- head ----
    final_kernel<<<NG, 64>>>(gp, Wl, bl, Wl2, bl2, (float*)d_out);
}